// round 11
// baseline (speedup 1.0000x reference)
#include <cuda_runtime.h>
#include <cuda_fp16.h>

// GraphConvolution: out = segment_sum(edge_val * (x@W)[edge_col] by edge_row) + b
// N=50000, E=800000, D_IN=D_OUT=96
// Strategy: [CSR build || dense GEMM(fp16 out)] fork-join; warp-per-row SpMM
// with cooperative payload load + shuffle broadcast; fp32 accum + bias.

#define DIN  96
#define DOUT 96
#define MAXN 50000
#define MAXE 800000

__device__ __half g_support[(size_t)MAXN * DOUT];
__device__ int    g_cnt[MAXN];
__device__ int    g_rowstart[MAXN];
__device__ int    g_fillpos[MAXN];
__device__ int2   g_edges[MAXE];
__device__ int    g_total;

// ---------------------------------------------------------------------------
__global__ void zero_kernel(int N) {
    int i = blockIdx.x * blockDim.x + threadIdx.x;
    if (i < N) g_cnt[i] = 0;
    if (i == 0) g_total = 0;
}

__global__ void hist_kernel(const int* __restrict__ er, int E) {
    int t  = blockIdx.x * blockDim.x + threadIdx.x;
    int e0 = t * 8;
    if (e0 + 8 <= E) {
        int4 a = __ldg((const int4*)er + t * 2);
        int4 b = __ldg((const int4*)er + t * 2 + 1);
        atomicAdd(&g_cnt[a.x], 1); atomicAdd(&g_cnt[a.y], 1);
        atomicAdd(&g_cnt[a.z], 1); atomicAdd(&g_cnt[a.w], 1);
        atomicAdd(&g_cnt[b.x], 1); atomicAdd(&g_cnt[b.y], 1);
        atomicAdd(&g_cnt[b.z], 1); atomicAdd(&g_cnt[b.w], 1);
    } else {
        for (int e = e0; e < E; e++) atomicAdd(&g_cnt[__ldg(er + e)], 1);
    }
}

__global__ void alloc_kernel(int N) {
    int i = blockIdx.x * blockDim.x + threadIdx.x;
    int lane = threadIdx.x & 31;
    int c = (i < N) ? g_cnt[i] : 0;
    int v = c;
#pragma unroll
    for (int d = 1; d < 32; d <<= 1) {
        int t = __shfl_up_sync(0xffffffffu, v, d);
        if (lane >= d) v += t;
    }
    int wtot = __shfl_sync(0xffffffffu, v, 31);
    int base = 0;
    if (lane == 31) base = atomicAdd(&g_total, wtot);
    base = __shfl_sync(0xffffffffu, base, 31);
    int start = base + v - c;
    if (i < N) { g_rowstart[i] = start; g_fillpos[i] = start; }
}

__global__ void bucket_kernel(const int*   __restrict__ er,
                              const int*   __restrict__ ec,
                              const float* __restrict__ ev, int E) {
    int t  = blockIdx.x * blockDim.x + threadIdx.x;
    int e0 = t * 8;
    if (e0 + 8 <= E) {
        int4   r0 = __ldg((const int4*)er + t * 2);
        int4   r1 = __ldg((const int4*)er + t * 2 + 1);
        int4   c0 = __ldg((const int4*)ec + t * 2);
        int4   c1 = __ldg((const int4*)ec + t * 2 + 1);
        float4 v0 = __ldg((const float4*)ev + t * 2);
        float4 v1 = __ldg((const float4*)ev + t * 2 + 1);
        int p0 = atomicAdd(&g_fillpos[r0.x], 1);
        int p1 = atomicAdd(&g_fillpos[r0.y], 1);
        int p2 = atomicAdd(&g_fillpos[r0.z], 1);
        int p3 = atomicAdd(&g_fillpos[r0.w], 1);
        int p4 = atomicAdd(&g_fillpos[r1.x], 1);
        int p5 = atomicAdd(&g_fillpos[r1.y], 1);
        int p6 = atomicAdd(&g_fillpos[r1.z], 1);
        int p7 = atomicAdd(&g_fillpos[r1.w], 1);
        g_edges[p0] = make_int2(c0.x, __float_as_int(v0.x));
        g_edges[p1] = make_int2(c0.y, __float_as_int(v0.y));
        g_edges[p2] = make_int2(c0.z, __float_as_int(v0.z));
        g_edges[p3] = make_int2(c0.w, __float_as_int(v0.w));
        g_edges[p4] = make_int2(c1.x, __float_as_int(v1.x));
        g_edges[p5] = make_int2(c1.y, __float_as_int(v1.y));
        g_edges[p6] = make_int2(c1.z, __float_as_int(v1.z));
        g_edges[p7] = make_int2(c1.w, __float_as_int(v1.w));
    } else {
        for (int e = e0; e < E; e++) {
            int r = __ldg(er + e);
            int p = atomicAdd(&g_fillpos[r], 1);
            g_edges[p] = make_int2(__ldg(ec + e), __float_as_int(__ldg(ev + e)));
        }
    }
}

// ---------------------------------------------------------------------------
// support = fp16(x @ W).  fp32 accumulation, fp16 store.
__global__ void __launch_bounds__(384)
gemm_kernel(const float* __restrict__ x,
            const float* __restrict__ w,
            __half* __restrict__ sup, int N) {
    __shared__ float4 Ws[DIN][DOUT / 4];

    int tid = threadIdx.x;
    const float4* w4 = (const float4*)w;
#pragma unroll
    for (int i = tid; i < DIN * DOUT / 4; i += 384)
        Ws[i / (DOUT / 4)][i % (DOUT / 4)] = w4[i];
    __syncthreads();

    int c4 = tid % 24;
    int r0 = blockIdx.x * 64 + (tid / 24) * 4;

    const float4* xr[4];
    bool valid[4];
#pragma unroll
    for (int j = 0; j < 4; j++) {
        int row  = r0 + j;
        valid[j] = (row < N);
        int rowc = valid[j] ? row : (N - 1);
        xr[j] = (const float4*)(x + (size_t)rowc * DIN);
    }

    float4 acc[4];
#pragma unroll
    for (int j = 0; j < 4; j++) acc[j] = make_float4(0.f, 0.f, 0.f, 0.f);

#pragma unroll 4
    for (int kk = 0; kk < DIN / 4; kk++) {
        float4 xv[4];
#pragma unroll
        for (int j = 0; j < 4; j++) xv[j] = __ldg(xr[j] + kk);
#pragma unroll
        for (int t = 0; t < 4; t++) {
            float4 wv = Ws[kk * 4 + t][c4];
#pragma unroll
            for (int j = 0; j < 4; j++) {
                float xs = (t == 0) ? xv[j].x : (t == 1) ? xv[j].y
                                              : (t == 2) ? xv[j].z : xv[j].w;
                acc[j].x += xs * wv.x;
                acc[j].y += xs * wv.y;
                acc[j].z += xs * wv.z;
                acc[j].w += xs * wv.w;
            }
        }
    }

#pragma unroll
    for (int j = 0; j < 4; j++) {
        if (valid[j]) {
            __half2 p0 = __floats2half2_rn(acc[j].x, acc[j].y);
            __half2 p1 = __floats2half2_rn(acc[j].z, acc[j].w);
            uint2 u;
            u.x = *(const unsigned int*)&p0;
            u.y = *(const unsigned int*)&p1;
            ((uint2*)(sup + (size_t)(r0 + j) * DOUT))[c4] = u;
        }
    }
}

// ---------------------------------------------------------------------------
// SpMM + bias: ONE WARP PER ROW. Payload loaded cooperatively (1 coalesced
// LDG.64 per 32 edges), broadcast by shuffle; lanes 0-23 gather uint2 (4
// halves) and accumulate fp32; single float4 store.
__global__ void __launch_bounds__(256)
spmm_kernel(const __half* __restrict__ sup,
            const float* __restrict__ b,
            float* __restrict__ out, int N) {
    int warp = (blockIdx.x * 256 + threadIdx.x) >> 5;
    int lane = threadIdx.x & 31;
    if (warp >= N) return;
    int row = warp;

    int st  = g_rowstart[row];
    int len = g_cnt[row];
    bool act = (lane < 24);

    float4 acc = make_float4(0.f, 0.f, 0.f, 0.f);

    for (int base = 0; base < len; base += 32) {
        int m = len - base; if (m > 32) m = 32;
        int2 cv = make_int2(0, 0);
        if (lane < m) cv = __ldg((const int2*)g_edges + st + base + lane);

        int j = 0;
        for (; j + 4 <= m; j += 4) {
            int   c0 = __shfl_sync(0xffffffffu, cv.x, j + 0);
            int   c1 = __shfl_sync(0xffffffffu, cv.x, j + 1);
            int   c2 = __shfl_sync(0xffffffffu, cv.x, j + 2);
            int   c3 = __shfl_sync(0xffffffffu, cv.x, j + 3);
            float v0 = __int_as_float(__shfl_sync(0xffffffffu, cv.y, j + 0));
            float v1 = __int_as_float(__shfl_sync(0xffffffffu, cv.y, j + 1));
            float v2 = __int_as_float(__shfl_sync(0xffffffffu, cv.y, j + 2));
            float v3 = __int_as_float(__shfl_sync(0xffffffffu, cv.y, j + 3));
            if (act) {
                uint2 u0 = __ldg((const uint2*)(sup + (size_t)c0 * DOUT) + lane);
                uint2 u1 = __ldg((const uint2*)(sup + (size_t)c1 * DOUT) + lane);
                uint2 u2 = __ldg((const uint2*)(sup + (size_t)c2 * DOUT) + lane);
                uint2 u3 = __ldg((const uint2*)(sup + (size_t)c3 * DOUT) + lane);
                float2 a0 = __half22float2(*(const __half2*)&u0.x);
                float2 q0 = __half22float2(*(const __half2*)&u0.y);
                float2 a1 = __half22float2(*(const __half2*)&u1.x);
                float2 q1 = __half22float2(*(const __half2*)&u1.y);
                float2 a2 = __half22float2(*(const __half2*)&u2.x);
                float2 q2 = __half22float2(*(const __half2*)&u2.y);
                float2 a3 = __half22float2(*(const __half2*)&u3.x);
                float2 q3 = __half22float2(*(const __half2*)&u3.y);
                acc.x += v0 * a0.x; acc.y += v0 * a0.y; acc.z += v0 * q0.x; acc.w += v0 * q0.y;
                acc.x += v1 * a1.x; acc.y += v1 * a1.y; acc.z += v1 * q1.x; acc.w += v1 * q1.y;
                acc.x += v2 * a2.x; acc.y += v2 * a2.y; acc.z += v2 * q2.x; acc.w += v2 * q2.y;
                acc.x += v3 * a3.x; acc.y += v3 * a3.y; acc.z += v3 * q3.x; acc.w += v3 * q3.y;
            }
        }
        for (; j < m; j++) {
            int   c0 = __shfl_sync(0xffffffffu, cv.x, j);
            float v0 = __int_as_float(__shfl_sync(0xffffffffu, cv.y, j));
            if (act) {
                uint2 u0 = __ldg((const uint2*)(sup + (size_t)c0 * DOUT) + lane);
                float2 a0 = __half22float2(*(const __half2*)&u0.x);
                float2 q0 = __half22float2(*(const __half2*)&u0.y);
                acc.x += v0 * a0.x; acc.y += v0 * a0.y;
                acc.z += v0 * q0.x; acc.w += v0 * q0.y;
            }
        }
    }

    if (act) {
        float4 bb = __ldg((const float4*)b + lane);
        acc.x += bb.x; acc.y += bb.y; acc.z += bb.z; acc.w += bb.w;
        ((float4*)(out + (size_t)row * DOUT))[lane] = acc;
    }
}

// ---------------------------------------------------------------------------
extern "C" void kernel_launch(void* const* d_in, const int* in_sizes, int n_in,
                              void* d_out, int out_size) {
    const float* x      = (const float*)d_in[0];
    const int*   e_row  = (const int*)  d_in[1];
    const int*   e_col  = (const int*)  d_in[2];
    const float* e_val  = (const float*)d_in[3];
    const float* weight = (const float*)d_in[4];
    const float* bias   = (const float*)d_in[5];
    float*       out    = (float*)d_out;

    int N = in_sizes[0] / DIN;
    int E = in_sizes[1];

    __half* sup;
    cudaGetSymbolAddress((void**)&sup, g_support);

    static cudaStream_t s_build = nullptr;
    static cudaEvent_t  ev_fork = nullptr, ev_build = nullptr;
    static bool init_done = false;
    if (!init_done) {
        init_done = true;
        cudaStreamCreateWithFlags(&s_build, cudaStreamNonBlocking);
        cudaEventCreateWithFlags(&ev_fork,  cudaEventDisableTiming);
        cudaEventCreateWithFlags(&ev_build, cudaEventDisableTiming);
    }

    int e8 = (E + 7) / 8;

    if (s_build && ev_fork && ev_build) {
        cudaEventRecord(ev_fork, 0);
        cudaStreamWaitEvent(s_build, ev_fork, 0);

        zero_kernel  <<<(N + 255) / 256, 256, 0, s_build>>>(N);
        hist_kernel  <<<(e8 + 255) / 256, 256, 0, s_build>>>(e_row, E);
        alloc_kernel <<<(N + 255) / 256, 256, 0, s_build>>>(N);
        bucket_kernel<<<(e8 + 255) / 256, 256, 0, s_build>>>(e_row, e_col, e_val, E);
        cudaEventRecord(ev_build, s_build);

        gemm_kernel<<<(N + 63) / 64, 384>>>(x, weight, sup, N);

        cudaStreamWaitEvent(0, ev_build, 0);
    } else {
        zero_kernel  <<<(N + 255) / 256, 256>>>(N);
        hist_kernel  <<<(e8 + 255) / 256, 256>>>(e_row, E);
        alloc_kernel <<<(N + 255) / 256, 256>>>(N);
        bucket_kernel<<<(e8 + 255) / 256, 256>>>(e_row, e_col, e_val, E);
        gemm_kernel  <<<(N + 63) / 64, 384>>>(x, weight, sup, N);
    }

    // one warp per row: 8 rows per 256-thread block
    spmm_kernel<<<(N + 7) / 8, 256>>>(sup, bias, out, N);
}